// round 15
// baseline (speedup 1.0000x reference)
#include <cuda_runtime.h>

#define KCODES 256
#define DIM 32
#define TPB 128
#define NTILES 4096          // 524288 / 128 tokens per CTA
#define ASTRIDE 33           // padded A row stride (words)
#define CANDCAP 6

typedef unsigned u32;
typedef unsigned long long u64;

__global__ void vq_zero_counts(float* counts) {
    counts[threadIdx.x] = 0.0f;
}

__device__ __forceinline__ u32 to_tf32(float f) {
    u32 u;
    asm("cvt.rna.tf32.f32 %0, %1;" : "=r"(u) : "f"(f));
    return u;
}

__device__ __forceinline__ void mma_tf32(float d[4], const u32 a[4], u32 b0, u32 b1) {
    asm volatile(
        "mma.sync.aligned.m16n8k8.row.col.f32.tf32.tf32.f32 "
        "{%0,%1,%2,%3},{%4,%5,%6,%7},{%8,%9},{%0,%1,%2,%3};"
        : "+f"(d[0]), "+f"(d[1]), "+f"(d[2]), "+f"(d[3])
        : "r"(a[0]), "r"(a[1]), "r"(a[2]), "r"(a[3]), "r"(b0), "r"(b1));
}

// s for one 8-code chunk (both m-tiles). Identical op order in both passes.
__device__ __forceinline__ void calc_s(
    const u64 bp[4], const u32 afr[2][4][4],
    float c2a, float c2b, float s[2][4])
{
    u32 b0[4], b1[4];
    #pragma unroll
    for (int ks = 0; ks < 4; ks++) { b0[ks] = (u32)bp[ks]; b1[ks] = (u32)(bp[ks] >> 32); }
    #pragma unroll
    for (int mt = 0; mt < 2; mt++) {
        float dA[4] = {0.f, 0.f, 0.f, 0.f};
        float dB[4] = {0.f, 0.f, 0.f, 0.f};
        mma_tf32(dA, afr[mt][0], b0[0], b1[0]);
        mma_tf32(dB, afr[mt][2], b0[2], b1[2]);
        mma_tf32(dA, afr[mt][1], b0[1], b1[1]);
        mma_tf32(dB, afr[mt][3], b0[3], b1[3]);
        s[mt][0] = __fmaf_rn(-2.0f, __fadd_rn(dA[0], dB[0]), c2a);
        s[mt][1] = __fmaf_rn(-2.0f, __fadd_rn(dA[1], dB[1]), c2b);
        s[mt][2] = __fmaf_rn(-2.0f, __fadd_rn(dA[2], dB[2]), c2a);
        s[mt][3] = __fmaf_rn(-2.0f, __fadd_rn(dA[3], dB[3]), c2b);
    }
}

__global__ __launch_bounds__(TPB, 4) void vq_tc(
    const float* __restrict__ x,
    const float* __restrict__ cb,
    float* __restrict__ out_rot,
    float* __restrict__ out_idx,
    float* __restrict__ out_counts)
{
    extern __shared__ __align__(16) u32 smem_dyn[];
    u64* Bq = reinterpret_cast<u64*>(smem_dyn);   // 32c x 4ks x 32lane u64 = 32 KB
    u32* As = smem_dyn + 8192;                    // 128 x 33 words

    __shared__ float c2_s[KCODES];
    __shared__ float hist[KCODES];
    __shared__ float best_s[TPB];
    __shared__ float thr_s[TPB];
    __shared__ int   cand_cnt[TPB];
    __shared__ int   cand[TPB * CANDCAP];

    const int tid  = threadIdx.x;
    const int lane = tid & 31;
    const int wid  = tid >> 5;
    const int gid  = lane >> 2;
    const int tig  = lane & 3;
    const int m0   = wid * 32;

    const long long tok0 = (long long)blockIdx.x * TPB;

    // ---- Stage A: token tid; exact x2 (sequential, reference order); tf32 copy ----
    // xr is NOT kept live through the MMA loops (reloaded later) to cap registers.
    float x2;
    {
        const float4* xp = reinterpret_cast<const float4*>(x + (tok0 + tid) * DIM);
        float row[DIM];
        #pragma unroll
        for (int j = 0; j < 8; j++) {
            float4 v = __ldg(xp + j);
            row[4*j+0] = v.x; row[4*j+1] = v.y; row[4*j+2] = v.z; row[4*j+3] = v.w;
        }
        float s = 0.0f;
        #pragma unroll
        for (int d = 0; d < DIM; d++)
            s = __fadd_rn(s, __fmul_rn(row[d], row[d]));
        x2 = s;
        #pragma unroll
        for (int d = 0; d < DIM; d++)
            As[tid * ASTRIDE + d] = to_tf32(row[d]);
    }

    // ---- Stage B: exact c2 (2 rows/thread); Bq fragment-paired tf32 ----
    #pragma unroll
    for (int rr = 0; rr < 2; rr++) {
        const int r = tid + rr * TPB;
        const float4* src = reinterpret_cast<const float4*>(cb + r * DIM);
        float row[DIM];
        #pragma unroll
        for (int j = 0; j < 8; j++) {
            float4 v = __ldg(src + j);
            row[4*j+0] = v.x; row[4*j+1] = v.y; row[4*j+2] = v.z; row[4*j+3] = v.w;
        }
        float s = 0.0f;
        #pragma unroll
        for (int d = 0; d < DIM; d++)
            s = __fadd_rn(s, __fmul_rn(row[d], row[d]));
        c2_s[r] = s;
        hist[r] = 0.0f;
    }
    #pragma unroll
    for (int ee = 0; ee < 32; ee++) {
        const int e  = tid + ee * TPB;
        const int le = e & 31;
        const int ks = (e >> 5) & 3;
        const int c  = e >> 7;
        const int r  = c * 8 + (le >> 2);
        const int k0 = ks * 8 + (le & 3);
        u32 w0 = to_tf32(__ldg(cb + r * DIM + k0));
        u32 w1 = to_tf32(__ldg(cb + r * DIM + k0 + 4));
        Bq[e] = (u64)w0 | ((u64)w1 << 32);
    }
    __syncthreads();

    // ---- A fragments ----
    u32 afr[2][4][4];
    #pragma unroll
    for (int mt = 0; mt < 2; mt++) {
        const int r0 = m0 + mt * 16 + gid;
        #pragma unroll
        for (int ks = 0; ks < 4; ks++) {
            const int k0 = ks * 8 + tig;
            afr[mt][ks][0] = As[ r0      * ASTRIDE + k0];
            afr[mt][ks][1] = As[(r0 + 8) * ASTRIDE + k0];
            afr[mt][ks][2] = As[ r0      * ASTRIDE + k0 + 4];
            afr[mt][ks][3] = As[(r0 + 8) * ASTRIDE + k0 + 4];
        }
    }

    // ---- Pass 1: per-token min, unrolled x2 (two chunks in flight) ----
    float mn[2][2] = {{3.4e38f, 3.4e38f}, {3.4e38f, 3.4e38f}};
    #pragma unroll 1
    for (int c = 0; c < 32; c += 2) {
        u64 bpA[4], bpB[4];
        #pragma unroll
        for (int ks = 0; ks < 4; ks++) {
            bpA[ks] = Bq[( c      * 4 + ks) * 32 + lane];
            bpB[ks] = Bq[((c + 1) * 4 + ks) * 32 + lane];
        }
        const float c2a0 = c2_s[c * 8 + tig * 2];
        const float c2b0 = c2_s[c * 8 + tig * 2 + 1];
        const float c2a1 = c2_s[(c + 1) * 8 + tig * 2];
        const float c2b1 = c2_s[(c + 1) * 8 + tig * 2 + 1];
        float sA[2][4], sB[2][4];
        calc_s(bpA, afr, c2a0, c2b0, sA);
        calc_s(bpB, afr, c2a1, c2b1, sB);
        #pragma unroll
        for (int mt = 0; mt < 2; mt++) {
            mn[mt][0] = fminf(mn[mt][0], fminf(fminf(sA[mt][0], sA[mt][1]), fminf(sB[mt][0], sB[mt][1])));
            mn[mt][1] = fminf(mn[mt][1], fminf(fminf(sA[mt][2], sA[mt][3]), fminf(sB[mt][2], sB[mt][3])));
        }
    }
    #pragma unroll
    for (int mt = 0; mt < 2; mt++) {
        #pragma unroll
        for (int h = 0; h < 2; h++) {
            float v = mn[mt][h];
            v = fminf(v, __shfl_xor_sync(0xFFFFFFFFu, v, 1));
            v = fminf(v, __shfl_xor_sync(0xFFFFFFFFu, v, 2));
            mn[mt][h] = v;
        }
    }
    if (tig == 0) {
        best_s[m0 + gid]      = mn[0][0];
        best_s[m0 + gid + 8]  = mn[0][1];
        best_s[m0 + gid + 16] = mn[1][0];
        best_s[m0 + gid + 24] = mn[1][1];
    }
    __syncthreads();

    {
        thr_s[tid] = best_s[tid] + __fmaf_rn(sqrtf(x2), 1e-4f, 4e-5f);
        cand_cnt[tid] = 0;
    }
    __syncthreads();

    // ---- Pass 2: identical MMAs (same calc_s), unrolled x2; flag candidates ----
    const float tA_lo = thr_s[m0 + gid];
    const float tA_hi = thr_s[m0 + gid + 8];
    const float tB_lo = thr_s[m0 + gid + 16];
    const float tB_hi = thr_s[m0 + gid + 24];

    #define FLAG(sv, col0)                                                          \
        {                                                                           \
            if (sv[0][0] <= tA_lo) { int sl = atomicAdd(&cand_cnt[m0 + gid], 1);        if (sl < CANDCAP) cand[(m0 + gid) * CANDCAP + sl] = (col0); }      \
            if (sv[0][1] <= tA_lo) { int sl = atomicAdd(&cand_cnt[m0 + gid], 1);        if (sl < CANDCAP) cand[(m0 + gid) * CANDCAP + sl] = (col0) + 1; }  \
            if (sv[0][2] <= tA_hi) { int sl = atomicAdd(&cand_cnt[m0 + gid + 8], 1);    if (sl < CANDCAP) cand[(m0 + gid + 8) * CANDCAP + sl] = (col0); }  \
            if (sv[0][3] <= tA_hi) { int sl = atomicAdd(&cand_cnt[m0 + gid + 8], 1);    if (sl < CANDCAP) cand[(m0 + gid + 8) * CANDCAP + sl] = (col0) + 1; } \
            if (sv[1][0] <= tB_lo) { int sl = atomicAdd(&cand_cnt[m0 + gid + 16], 1);   if (sl < CANDCAP) cand[(m0 + gid + 16) * CANDCAP + sl] = (col0); } \
            if (sv[1][1] <= tB_lo) { int sl = atomicAdd(&cand_cnt[m0 + gid + 16], 1);   if (sl < CANDCAP) cand[(m0 + gid + 16) * CANDCAP + sl] = (col0) + 1; } \
            if (sv[1][2] <= tB_hi) { int sl = atomicAdd(&cand_cnt[m0 + gid + 24], 1);   if (sl < CANDCAP) cand[(m0 + gid + 24) * CANDCAP + sl] = (col0); } \
            if (sv[1][3] <= tB_hi) { int sl = atomicAdd(&cand_cnt[m0 + gid + 24], 1);   if (sl < CANDCAP) cand[(m0 + gid + 24) * CANDCAP + sl] = (col0) + 1; } \
        }

    #pragma unroll 1
    for (int c = 0; c < 32; c += 2) {
        u64 bpA[4], bpB[4];
        #pragma unroll
        for (int ks = 0; ks < 4; ks++) {
            bpA[ks] = Bq[( c      * 4 + ks) * 32 + lane];
            bpB[ks] = Bq[((c + 1) * 4 + ks) * 32 + lane];
        }
        const int colA = c * 8 + tig * 2;
        const int colB = (c + 1) * 8 + tig * 2;
        float sA[2][4], sB[2][4];
        calc_s(bpA, afr, c2_s[colA], c2_s[colA + 1], sA);
        calc_s(bpB, afr, c2_s[colB], c2_s[colB + 1], sB);
        FLAG(sA, colA)
        FLAG(sB, colB)
    }
    #undef FLAG
    __syncthreads();

    // ---- Reload x (identical values -> bit-identical chains) ----
    float xr[DIM];
    {
        const float4* xp = reinterpret_cast<const float4*>(x + (tok0 + tid) * DIM);
        #pragma unroll
        for (int j = 0; j < 8; j++) {
            float4 v = __ldg(xp + j);
            xr[4*j+0] = v.x; xr[4*j+1] = v.y; xr[4*j+2] = v.z; xr[4*j+3] = v.w;
        }
    }

    // ---- Exact recheck (R1 bit-exact d2; first-index ties) ----
    int bi = 0;
    {
        const int cnt = cand_cnt[tid];
        float bestE = 3.4e38f;
        if (cnt <= CANDCAP) {
            for (int i = 0; i < cnt; i++) {
                const int k = cand[tid * CANDCAP + i];
                const float4* qr = reinterpret_cast<const float4*>(cb + k * DIM);
                float dotx = 0.0f;
                #pragma unroll
                for (int jj = 0; jj < 8; jj++) {
                    float4 q4 = __ldg(qr + jj);
                    dotx = __fmaf_rn(xr[4*jj+0], q4.x, dotx);
                    dotx = __fmaf_rn(xr[4*jj+1], q4.y, dotx);
                    dotx = __fmaf_rn(xr[4*jj+2], q4.z, dotx);
                    dotx = __fmaf_rn(xr[4*jj+3], q4.w, dotx);
                }
                float d2 = __fadd_rn(__fadd_rn(x2, __fmul_rn(-2.0f, dotx)), c2_s[k]);
                if (d2 < bestE || (d2 == bestE && k < bi)) { bestE = d2; bi = k; }
            }
        } else {
            for (int k = 0; k < KCODES; k++) {
                const float4* qr = reinterpret_cast<const float4*>(cb + k * DIM);
                float dotx = 0.0f;
                #pragma unroll
                for (int jj = 0; jj < 8; jj++) {
                    float4 q4 = __ldg(qr + jj);
                    dotx = __fmaf_rn(xr[4*jj+0], q4.x, dotx);
                    dotx = __fmaf_rn(xr[4*jj+1], q4.y, dotx);
                    dotx = __fmaf_rn(xr[4*jj+2], q4.z, dotx);
                    dotx = __fmaf_rn(xr[4*jj+3], q4.w, dotx);
                }
                float d2 = __fadd_rn(__fadd_rn(x2, __fmul_rn(-2.0f, dotx)), c2_s[k]);
                if (d2 < bestE) { bestE = d2; bi = k; }
            }
        }
    }

    // ---- Epilogue: histogram + rotation-trick output ----
    atomicAdd(&hist[bi], 1.0f);
    {
        float qv[DIM];
        const float4* qrow = reinterpret_cast<const float4*>(cb + bi * DIM);
        #pragma unroll
        for (int j = 0; j < 8; j++) {
            float4 v = __ldg(qrow + j);
            qv[4*j+0] = v.x; qv[4*j+1] = v.y; qv[4*j+2] = v.z; qv[4*j+3] = v.w;
        }
        float q2 = 0.f, dotq = 0.f;
        #pragma unroll
        for (int d = 0; d < DIM; d++) {
            q2   = __fmaf_rn(qv[d], qv[d], q2);
            dotq = __fmaf_rn(xr[d], qv[d], dotq);
        }
        const float eps = 1e-6f;
        float inx = 1.0f / fmaxf(sqrtf(x2), eps);
        float inq = 1.0f / fmaxf(sqrtf(q2), eps);
        float u2  = x2 * inx * inx;
        float qh2 = q2 * inq * inq;
        float uq  = dotq * inx * inq;
        float w2  = u2 + qh2 + 2.0f * uq;
        float iw  = 1.0f / fmaxf(sqrtf(w2), eps);
        float ew  = (x2 * inx + dotq * inq) * iw;
        float eu  = x2 * inx;
        float a   = -2.0f * ew * iw;
        float s1  = 1.0f + a * inx;
        float s2  = (a + 2.0f * eu) * inq;

        float4* rp = reinterpret_cast<float4*>(out_rot + (tok0 + tid) * DIM);
        #pragma unroll
        for (int j = 0; j < 8; j++) {
            float4 v;
            v.x = xr[4*j+0] * s1 + qv[4*j+0] * s2;
            v.y = xr[4*j+1] * s1 + qv[4*j+1] * s2;
            v.z = xr[4*j+2] * s1 + qv[4*j+2] * s2;
            v.w = xr[4*j+3] * s1 + qv[4*j+3] * s2;
            rp[j] = v;
        }
        out_idx[tok0 + tid] = (float)bi;
    }

    // ---- Flush histogram ----
    __syncthreads();
    #pragma unroll
    for (int rr = 0; rr < 2; rr++)
        atomicAdd(&out_counts[tid + rr * TPB], hist[tid + rr * TPB]);
}

extern "C" void kernel_launch(void* const* d_in, const int* in_sizes, int n_in,
                              void* d_out, int out_size) {
    const float* x  = (const float*)d_in[0];
    const float* cb = (const float*)d_in[1];
    float* out = (float*)d_out;

    const int N = in_sizes[0] / DIM;            // 524288
    float* rot    = out;
    float* idx    = out + (size_t)N * DIM;
    float* counts = idx + N;

    const int dyn = 32768 + TPB * ASTRIDE * 4;  // Bq + As = 49664 B
    cudaFuncSetAttribute(vq_tc, cudaFuncAttributeMaxDynamicSharedMemorySize, dyn);
    vq_zero_counts<<<1, KCODES>>>(counts);
    vq_tc<<<NTILES, TPB, dyn>>>(x, cb, rot, idx, counts);
}

// round 16
// speedup vs baseline: 1.3629x; 1.3629x over previous
#include <cuda_runtime.h>

#define KCODES 256
#define DIM 32
#define TPB 128
#define NTILES 4096          // 524288 / 128 tokens per CTA
#define XST 33               // xS row stride (words): row-per-lane reads conflict-free
#define CST 34               // cbS row stride (words): 2-way max on frag pattern
#define CANDCAP 4

typedef unsigned u32;

__global__ void vq_zero_counts(float* counts) {
    counts[threadIdx.x] = 0.0f;
}

__device__ __forceinline__ u32 to_tf32(float f) {
    u32 u;
    asm("cvt.rna.tf32.f32 %0, %1;" : "=r"(u) : "f"(f));
    return u;
}

__device__ __forceinline__ void mma_tf32(float d[4], const u32 a[4], u32 b0, u32 b1) {
    asm volatile(
        "mma.sync.aligned.m16n8k8.row.col.f32.tf32.tf32.f32 "
        "{%0,%1,%2,%3},{%4,%5,%6,%7},{%8,%9},{%0,%1,%2,%3};"
        : "+f"(d[0]), "+f"(d[1]), "+f"(d[2]), "+f"(d[3])
        : "r"(a[0]), "r"(a[1]), "r"(a[2]), "r"(a[3]), "r"(b0), "r"(b1));
}

// s for one 8-code chunk (both m-tiles). Identical op order in both passes.
__device__ __forceinline__ void calc_s(
    const u32 b0[4], const u32 b1[4], const u32 afr[2][4][4],
    float c2a, float c2b, float s[2][4])
{
    #pragma unroll
    for (int mt = 0; mt < 2; mt++) {
        float dA[4] = {0.f, 0.f, 0.f, 0.f};
        float dB[4] = {0.f, 0.f, 0.f, 0.f};
        mma_tf32(dA, afr[mt][0], b0[0], b1[0]);
        mma_tf32(dB, afr[mt][2], b0[2], b1[2]);
        mma_tf32(dA, afr[mt][1], b0[1], b1[1]);
        mma_tf32(dB, afr[mt][3], b0[3], b1[3]);
        s[mt][0] = __fmaf_rn(-2.0f, __fadd_rn(dA[0], dB[0]), c2a);
        s[mt][1] = __fmaf_rn(-2.0f, __fadd_rn(dA[1], dB[1]), c2b);
        s[mt][2] = __fmaf_rn(-2.0f, __fadd_rn(dA[2], dB[2]), c2a);
        s[mt][3] = __fmaf_rn(-2.0f, __fadd_rn(dA[3], dB[3]), c2b);
    }
}

__global__ __launch_bounds__(TPB, 4) void vq_tc(
    const float* __restrict__ x,
    const float* __restrict__ cb,
    float* __restrict__ out_rot,
    float* __restrict__ out_idx,
    float* __restrict__ out_counts)
{
    extern __shared__ __align__(16) float smem_dyn[];
    float* xS  = smem_dyn;                 // 128 x 33 floats = 16896 B
    float* cbS = smem_dyn + TPB * XST;     // 256 x 34 floats = 34816 B

    __shared__ float c2_s[KCODES];
    __shared__ float hist[KCODES];
    __shared__ float thr_s[TPB];           // holds best, then threshold (in place)
    __shared__ int   cand_cnt[TPB];
    __shared__ int   cand[TPB * CANDCAP];

    const int tid  = threadIdx.x;
    const int lane = tid & 31;
    const int wid  = tid >> 5;
    const int gid  = lane >> 2;
    const int tig  = lane & 3;
    const int m0   = wid * 32;

    const long long tok0 = (long long)blockIdx.x * TPB;

    // ---- Coalesced staging: x tile (4096 floats) and codebook (8192 floats) ----
    {
        const float4* xg = reinterpret_cast<const float4*>(x + tok0 * DIM);
        #pragma unroll
        for (int j = 0; j < 8; j++) {
            const int idx = j * TPB + tid;        // coalesced float4 stream
            float4 v = __ldg(xg + idx);
            const int row = idx >> 3;
            const int off = (idx & 7) * 4;
            xS[row * XST + off + 0] = v.x;
            xS[row * XST + off + 1] = v.y;
            xS[row * XST + off + 2] = v.z;
            xS[row * XST + off + 3] = v.w;
        }
        const float4* cg = reinterpret_cast<const float4*>(cb);
        #pragma unroll
        for (int j = 0; j < 16; j++) {
            const int idx = j * TPB + tid;
            float4 v = __ldg(cg + idx);
            const int row = idx >> 3;
            const int off = (idx & 7) * 4;
            cbS[row * CST + off + 0] = v.x;
            cbS[row * CST + off + 1] = v.y;
            cbS[row * CST + off + 2] = v.z;
            cbS[row * CST + off + 3] = v.w;
        }
    }
    __syncthreads();

    // ---- x2 (token tid) and c2 (2 rows/thread): exact sequential chains from smem ----
    float x2;
    {
        float s = 0.0f;
        #pragma unroll
        for (int d = 0; d < DIM; d++) {
            float v = xS[tid * XST + d];
            s = __fadd_rn(s, __fmul_rn(v, v));
        }
        x2 = s;
    }
    #pragma unroll
    for (int rr = 0; rr < 2; rr++) {
        const int r = tid + rr * TPB;
        float s = 0.0f;
        #pragma unroll
        for (int d = 0; d < DIM; d++) {
            float v = cbS[r * CST + d];
            s = __fadd_rn(s, __fmul_rn(v, v));
        }
        c2_s[r] = s;
        hist[r] = 0.0f;
    }
    __syncthreads();

    // ---- A fragments from xS (cvt in registers) ----
    u32 afr[2][4][4];
    #pragma unroll
    for (int mt = 0; mt < 2; mt++) {
        const int r0 = m0 + mt * 16 + gid;
        #pragma unroll
        for (int ks = 0; ks < 4; ks++) {
            const int k0 = ks * 8 + tig;
            afr[mt][ks][0] = to_tf32(xS[ r0      * XST + k0]);
            afr[mt][ks][1] = to_tf32(xS[(r0 + 8) * XST + k0]);
            afr[mt][ks][2] = to_tf32(xS[ r0      * XST + k0 + 4]);
            afr[mt][ks][3] = to_tf32(xS[(r0 + 8) * XST + k0 + 4]);
        }
    }

    // ---- Pass 1: per-token min of s = c2 - 2*dot ----
    float mn[2][2] = {{3.4e38f, 3.4e38f}, {3.4e38f, 3.4e38f}};
    #pragma unroll 1
    for (int c = 0; c < 32; c++) {
        u32 b0[4], b1[4];
        const int rB = c * 8 + gid;
        #pragma unroll
        for (int ks = 0; ks < 4; ks++) {
            b0[ks] = to_tf32(cbS[rB * CST + ks * 8 + tig]);
            b1[ks] = to_tf32(cbS[rB * CST + ks * 8 + tig + 4]);
        }
        const float c2a = c2_s[c * 8 + tig * 2];
        const float c2b = c2_s[c * 8 + tig * 2 + 1];
        float s[2][4];
        calc_s(b0, b1, afr, c2a, c2b, s);
        #pragma unroll
        for (int mt = 0; mt < 2; mt++) {
            mn[mt][0] = fminf(mn[mt][0], fminf(s[mt][0], s[mt][1]));
            mn[mt][1] = fminf(mn[mt][1], fminf(s[mt][2], s[mt][3]));
        }
    }
    #pragma unroll
    for (int mt = 0; mt < 2; mt++) {
        #pragma unroll
        for (int h = 0; h < 2; h++) {
            float v = mn[mt][h];
            v = fminf(v, __shfl_xor_sync(0xFFFFFFFFu, v, 1));
            v = fminf(v, __shfl_xor_sync(0xFFFFFFFFu, v, 2));
            mn[mt][h] = v;
        }
    }
    if (tig == 0) {
        thr_s[m0 + gid]      = mn[0][0];
        thr_s[m0 + gid + 8]  = mn[0][1];
        thr_s[m0 + gid + 16] = mn[1][0];
        thr_s[m0 + gid + 24] = mn[1][1];
    }
    __syncthreads();

    // ---- Threshold in place (rigorous tf32 bound; same formula, passed bit-exact) ----
    {
        thr_s[tid] = thr_s[tid] + __fmaf_rn(sqrtf(x2), 1e-4f, 4e-5f);
        cand_cnt[tid] = 0;
    }
    __syncthreads();

    // ---- Pass 2: identical MMAs (same calc_s); flag candidates ----
    const float tA_lo = thr_s[m0 + gid];
    const float tA_hi = thr_s[m0 + gid + 8];
    const float tB_lo = thr_s[m0 + gid + 16];
    const float tB_hi = thr_s[m0 + gid + 24];
    #pragma unroll 1
    for (int c = 0; c < 32; c++) {
        u32 b0[4], b1[4];
        const int rB = c * 8 + gid;
        #pragma unroll
        for (int ks = 0; ks < 4; ks++) {
            b0[ks] = to_tf32(cbS[rB * CST + ks * 8 + tig]);
            b1[ks] = to_tf32(cbS[rB * CST + ks * 8 + tig + 4]);
        }
        const int col0 = c * 8 + tig * 2;
        const float c2a = c2_s[col0];
        const float c2b = c2_s[col0 + 1];
        float s[2][4];
        calc_s(b0, b1, afr, c2a, c2b, s);
        #pragma unroll
        for (int mt = 0; mt < 2; mt++) {
            const float tlo = mt ? tB_lo : tA_lo;
            const float thi = mt ? tB_hi : tA_hi;
            const int rlo = m0 + mt * 16 + gid;
            const int rhi = rlo + 8;
            if (s[mt][0] <= tlo) { int sl = atomicAdd(&cand_cnt[rlo], 1); if (sl < CANDCAP) cand[rlo * CANDCAP + sl] = col0; }
            if (s[mt][1] <= tlo) { int sl = atomicAdd(&cand_cnt[rlo], 1); if (sl < CANDCAP) cand[rlo * CANDCAP + sl] = col0 + 1; }
            if (s[mt][2] <= thi) { int sl = atomicAdd(&cand_cnt[rhi], 1); if (sl < CANDCAP) cand[rhi * CANDCAP + sl] = col0; }
            if (s[mt][3] <= thi) { int sl = atomicAdd(&cand_cnt[rhi], 1); if (sl < CANDCAP) cand[rhi * CANDCAP + sl] = col0 + 1; }
        }
    }
    __syncthreads();

    // ---- Load xr from smem (identical fp32 values -> bit-identical chains) ----
    float xr[DIM];
    #pragma unroll
    for (int d = 0; d < DIM; d++)
        xr[d] = xS[tid * XST + d];

    // ---- Exact recheck from cbS (R1 bit-exact d2; first-index ties) ----
    int bi = 0;
    {
        const int cnt = cand_cnt[tid];
        float bestE = 3.4e38f;
        if (cnt <= CANDCAP) {
            for (int i = 0; i < cnt; i++) {
                const int k = cand[tid * CANDCAP + i];
                const float2* qr = reinterpret_cast<const float2*>(cbS + k * CST);
                float dotx = 0.0f;
                #pragma unroll
                for (int jj = 0; jj < 16; jj++) {
                    float2 q2v = qr[jj];
                    dotx = __fmaf_rn(xr[2*jj],     q2v.x, dotx);
                    dotx = __fmaf_rn(xr[2*jj + 1], q2v.y, dotx);
                }
                float d2 = __fadd_rn(__fadd_rn(x2, __fmul_rn(-2.0f, dotx)), c2_s[k]);
                if (d2 < bestE || (d2 == bestE && k < bi)) { bestE = d2; bi = k; }
            }
        } else {
            // overflow: deterministic full exact scan, ascending k, strict <
            for (int k = 0; k < KCODES; k++) {
                const float2* qr = reinterpret_cast<const float2*>(cbS + k * CST);
                float dotx = 0.0f;
                #pragma unroll
                for (int jj = 0; jj < 16; jj++) {
                    float2 q2v = qr[jj];
                    dotx = __fmaf_rn(xr[2*jj],     q2v.x, dotx);
                    dotx = __fmaf_rn(xr[2*jj + 1], q2v.y, dotx);
                }
                float d2 = __fadd_rn(__fadd_rn(x2, __fmul_rn(-2.0f, dotx)), c2_s[k]);
                if (d2 < bestE) { bestE = d2; bi = k; }
            }
        }
    }

    // ---- Epilogue: histogram + rotation-trick output (codebook row from cbS) ----
    atomicAdd(&hist[bi], 1.0f);
    {
        float qv[DIM];
        const float2* qrow = reinterpret_cast<const float2*>(cbS + bi * CST);
        #pragma unroll
        for (int jj = 0; jj < 16; jj++) {
            float2 v = qrow[jj];
            qv[2*jj] = v.x; qv[2*jj + 1] = v.y;
        }
        float q2 = 0.f, dotq = 0.f;
        #pragma unroll
        for (int d = 0; d < DIM; d++) {
            q2   = __fmaf_rn(qv[d], qv[d], q2);
            dotq = __fmaf_rn(xr[d], qv[d], dotq);
        }
        const float eps = 1e-6f;
        float inx = 1.0f / fmaxf(sqrtf(x2), eps);
        float inq = 1.0f / fmaxf(sqrtf(q2), eps);
        float u2  = x2 * inx * inx;
        float qh2 = q2 * inq * inq;
        float uq  = dotq * inx * inq;
        float w2  = u2 + qh2 + 2.0f * uq;
        float iw  = 1.0f / fmaxf(sqrtf(w2), eps);
        float ew  = (x2 * inx + dotq * inq) * iw;
        float eu  = x2 * inx;
        float a   = -2.0f * ew * iw;
        float s1  = 1.0f + a * inx;
        float s2  = (a + 2.0f * eu) * inq;

        float4* rp = reinterpret_cast<float4*>(out_rot + (tok0 + tid) * DIM);
        #pragma unroll
        for (int j = 0; j < 8; j++) {
            float4 v;
            v.x = xr[4*j+0] * s1 + qv[4*j+0] * s2;
            v.y = xr[4*j+1] * s1 + qv[4*j+1] * s2;
            v.z = xr[4*j+2] * s1 + qv[4*j+2] * s2;
            v.w = xr[4*j+3] * s1 + qv[4*j+3] * s2;
            rp[j] = v;
        }
        out_idx[tok0 + tid] = (float)bi;
    }

    // ---- Flush histogram ----
    __syncthreads();
    #pragma unroll
    for (int rr = 0; rr < 2; rr++)
        atomicAdd(&out_counts[tid + rr * TPB], hist[tid + rr * TPB]);
}

extern "C" void kernel_launch(void* const* d_in, const int* in_sizes, int n_in,
                              void* d_out, int out_size) {
    const float* x  = (const float*)d_in[0];
    const float* cb = (const float*)d_in[1];
    float* out = (float*)d_out;

    const int N = in_sizes[0] / DIM;            // 524288
    float* rot    = out;
    float* idx    = out + (size_t)N * DIM;
    float* counts = idx + N;

    const int dyn = (TPB * XST + KCODES * CST) * 4;  // 16896 + 34816 = 51712 B
    cudaFuncSetAttribute(vq_tc, cudaFuncAttributeMaxDynamicSharedMemorySize, dyn);
    vq_zero_counts<<<1, KCODES>>>(counts);
    vq_tc<<<NTILES, TPB, dyn>>>(x, cb, rot, idx, counts);
}

// round 17
// speedup vs baseline: 1.3764x; 1.0099x over previous
#include <cuda_runtime.h>

#define KCODES 256
#define DIM 32
#define TPB 128
#define NTILES 4096          // 524288 / 128 tokens per CTA
#define XST 33               // xS row stride (floats)
#define CST 34               // cbS row stride (floats) = 17 u64 per row
#define CANDCAP 4

typedef unsigned u32;
typedef unsigned long long u64;

__global__ void vq_zero_counts(float* counts) {
    counts[threadIdx.x] = 0.0f;
}

__device__ __forceinline__ u32 to_tf32(float f) {
    u32 u;
    asm("cvt.rna.tf32.f32 %0, %1;" : "=r"(u) : "f"(f));
    return u;
}

__device__ __forceinline__ void mma_tf32(float d[4], const u32 a[4], u32 b0, u32 b1) {
    asm volatile(
        "mma.sync.aligned.m16n8k8.row.col.f32.tf32.tf32.f32 "
        "{%0,%1,%2,%3},{%4,%5,%6,%7},{%8,%9},{%0,%1,%2,%3};"
        : "+f"(d[0]), "+f"(d[1]), "+f"(d[2]), "+f"(d[3])
        : "r"(a[0]), "r"(a[1]), "r"(a[2]), "r"(a[3]), "r"(b0), "r"(b1));
}

// s for one 8-code chunk (both m-tiles). Identical op order in both passes.
__device__ __forceinline__ void calc_s(
    const u64 bp[4], const u32 afr[2][4][4],
    float c2a, float c2b, float s[2][4])
{
    u32 b0[4], b1[4];
    #pragma unroll
    for (int ks = 0; ks < 4; ks++) { b0[ks] = (u32)bp[ks]; b1[ks] = (u32)(bp[ks] >> 32); }
    #pragma unroll
    for (int mt = 0; mt < 2; mt++) {
        float dA[4] = {0.f, 0.f, 0.f, 0.f};
        float dB[4] = {0.f, 0.f, 0.f, 0.f};
        mma_tf32(dA, afr[mt][0], b0[0], b1[0]);
        mma_tf32(dB, afr[mt][2], b0[2], b1[2]);
        mma_tf32(dA, afr[mt][1], b0[1], b1[1]);
        mma_tf32(dB, afr[mt][3], b0[3], b1[3]);
        s[mt][0] = __fmaf_rn(-2.0f, __fadd_rn(dA[0], dB[0]), c2a);
        s[mt][1] = __fmaf_rn(-2.0f, __fadd_rn(dA[1], dB[1]), c2b);
        s[mt][2] = __fmaf_rn(-2.0f, __fadd_rn(dA[2], dB[2]), c2a);
        s[mt][3] = __fmaf_rn(-2.0f, __fadd_rn(dA[3], dB[3]), c2b);
    }
}

__global__ __launch_bounds__(TPB, 4) void vq_tc(
    const float* __restrict__ x,
    const float* __restrict__ cb,
    float* __restrict__ out_rot,
    float* __restrict__ out_idx,
    float* __restrict__ out_counts)
{
    extern __shared__ __align__(16) float smem_dyn[];
    float* xS  = smem_dyn;                                 // 128 x 33 floats
    float* cbS = smem_dyn + TPB * XST;                     // 256 x 34 floats (exact, then tf32 pairs)
    u64*   cbT = reinterpret_cast<u64*>(cbS);              // 256 x 17 u64 (same footprint)

    __shared__ float c2_s[KCODES];
    __shared__ float hist[KCODES];
    __shared__ float thr_s[TPB];
    __shared__ int   cand_cnt[TPB];
    __shared__ int   cand[TPB * CANDCAP];

    const int tid  = threadIdx.x;
    const int lane = tid & 31;
    const int wid  = tid >> 5;
    const int gid  = lane >> 2;
    const int tig  = lane & 3;
    const int m0   = wid * 32;

    const long long tok0 = (long long)blockIdx.x * TPB;

    // ---- Coalesced staging of x tile and exact codebook ----
    {
        const float4* xg = reinterpret_cast<const float4*>(x + tok0 * DIM);
        #pragma unroll
        for (int j = 0; j < 8; j++) {
            const int idx = j * TPB + tid;
            float4 v = __ldg(xg + idx);
            const int row = idx >> 3;
            const int off = (idx & 7) * 4;
            xS[row * XST + off + 0] = v.x;
            xS[row * XST + off + 1] = v.y;
            xS[row * XST + off + 2] = v.z;
            xS[row * XST + off + 3] = v.w;
        }
        const float4* cg = reinterpret_cast<const float4*>(cb);
        #pragma unroll
        for (int j = 0; j < 16; j++) {
            const int idx = j * TPB + tid;
            float4 v = __ldg(cg + idx);
            const int row = idx >> 3;
            const int off = (idx & 7) * 4;
            cbS[row * CST + off + 0] = v.x;
            cbS[row * CST + off + 1] = v.y;
            cbS[row * CST + off + 2] = v.z;
            cbS[row * CST + off + 3] = v.w;
        }
    }
    __syncthreads();

    // ---- x2 (exact sequential chain) for token tid ----
    float x2;
    {
        float s = 0.0f;
        #pragma unroll
        for (int d = 0; d < DIM; d++) {
            float v = xS[tid * XST + d];
            s = __fadd_rn(s, __fmul_rn(v, v));
        }
        x2 = s;
    }

    // ---- c2 (exact) + in-place tf32 pair conversion; 2 rows/thread ----
    // Row r footprint [r*136B, +136B) is touched only by its owning thread.
    #pragma unroll
    for (int rr = 0; rr < 2; rr++) {
        const int r = tid + rr * TPB;
        float row[DIM];
        #pragma unroll
        for (int d = 0; d < DIM; d++)
            row[d] = cbS[r * CST + d];
        float s = 0.0f;
        #pragma unroll
        for (int d = 0; d < DIM; d++)
            s = __fadd_rn(s, __fmul_rn(row[d], row[d]));
        c2_s[r] = s;
        hist[r] = 0.0f;
        // pair p = t*4 + k stores (tf32(row[k*8+t]), tf32(row[k*8+t+4]))
        #pragma unroll
        for (int t = 0; t < 4; t++)
            #pragma unroll
            for (int k = 0; k < 4; k++) {
                u64 w = (u64)to_tf32(row[k * 8 + t])
                      | ((u64)to_tf32(row[k * 8 + t + 4]) << 32);
                cbT[r * 17 + t * 4 + k] = w;
            }
    }
    __syncthreads();

    // ---- A fragments from exact xS (one-time CVT) ----
    u32 afr[2][4][4];
    #pragma unroll
    for (int mt = 0; mt < 2; mt++) {
        const int r0 = m0 + mt * 16 + gid;
        #pragma unroll
        for (int ks = 0; ks < 4; ks++) {
            const int k0 = ks * 8 + tig;
            afr[mt][ks][0] = to_tf32(xS[ r0      * XST + k0]);
            afr[mt][ks][1] = to_tf32(xS[(r0 + 8) * XST + k0]);
            afr[mt][ks][2] = to_tf32(xS[ r0      * XST + k0 + 4]);
            afr[mt][ks][3] = to_tf32(xS[(r0 + 8) * XST + k0 + 4]);
        }
    }

    // ---- Pass 1: per-token min of s = c2 - 2*dot ----
    float mn[2][2] = {{3.4e38f, 3.4e38f}, {3.4e38f, 3.4e38f}};
    #pragma unroll 1
    for (int c = 0; c < 32; c++) {
        u64 bp[4];
        const int rB = (c * 8 + gid) * 17 + tig * 4;
        #pragma unroll
        for (int ks = 0; ks < 4; ks++)
            bp[ks] = cbT[rB + ks];
        const float c2a = c2_s[c * 8 + tig * 2];
        const float c2b = c2_s[c * 8 + tig * 2 + 1];
        float s[2][4];
        calc_s(bp, afr, c2a, c2b, s);
        #pragma unroll
        for (int mt = 0; mt < 2; mt++) {
            mn[mt][0] = fminf(mn[mt][0], fminf(s[mt][0], s[mt][1]));
            mn[mt][1] = fminf(mn[mt][1], fminf(s[mt][2], s[mt][3]));
        }
    }
    #pragma unroll
    for (int mt = 0; mt < 2; mt++) {
        #pragma unroll
        for (int h = 0; h < 2; h++) {
            float v = mn[mt][h];
            v = fminf(v, __shfl_xor_sync(0xFFFFFFFFu, v, 1));
            v = fminf(v, __shfl_xor_sync(0xFFFFFFFFu, v, 2));
            mn[mt][h] = v;
        }
    }
    if (tig == 0) {
        thr_s[m0 + gid]      = mn[0][0];
        thr_s[m0 + gid + 8]  = mn[0][1];
        thr_s[m0 + gid + 16] = mn[1][0];
        thr_s[m0 + gid + 24] = mn[1][1];
    }
    __syncthreads();

    {
        thr_s[tid] = thr_s[tid] + __fmaf_rn(sqrtf(x2), 1e-4f, 4e-5f);
        cand_cnt[tid] = 0;
    }
    __syncthreads();

    // ---- Pass 2: identical MMAs; flag candidates ----
    const float tA_lo = thr_s[m0 + gid];
    const float tA_hi = thr_s[m0 + gid + 8];
    const float tB_lo = thr_s[m0 + gid + 16];
    const float tB_hi = thr_s[m0 + gid + 24];
    #pragma unroll 1
    for (int c = 0; c < 32; c++) {
        u64 bp[4];
        const int rB = (c * 8 + gid) * 17 + tig * 4;
        #pragma unroll
        for (int ks = 0; ks < 4; ks++)
            bp[ks] = cbT[rB + ks];
        const int col0 = c * 8 + tig * 2;
        const float c2a = c2_s[col0];
        const float c2b = c2_s[col0 + 1];
        float s[2][4];
        calc_s(bp, afr, c2a, c2b, s);
        #pragma unroll
        for (int mt = 0; mt < 2; mt++) {
            const float tlo = mt ? tB_lo : tA_lo;
            const float thi = mt ? tB_hi : tA_hi;
            const int rlo = m0 + mt * 16 + gid;
            const int rhi = rlo + 8;
            if (s[mt][0] <= tlo) { int sl = atomicAdd(&cand_cnt[rlo], 1); if (sl < CANDCAP) cand[rlo * CANDCAP + sl] = col0; }
            if (s[mt][1] <= tlo) { int sl = atomicAdd(&cand_cnt[rlo], 1); if (sl < CANDCAP) cand[rlo * CANDCAP + sl] = col0 + 1; }
            if (s[mt][2] <= thi) { int sl = atomicAdd(&cand_cnt[rhi], 1); if (sl < CANDCAP) cand[rhi * CANDCAP + sl] = col0; }
            if (s[mt][3] <= thi) { int sl = atomicAdd(&cand_cnt[rhi], 1); if (sl < CANDCAP) cand[rhi * CANDCAP + sl] = col0 + 1; }
        }
    }
    __syncthreads();

    // ---- xr from exact xS ----
    float xr[DIM];
    #pragma unroll
    for (int d = 0; d < DIM; d++)
        xr[d] = xS[tid * XST + d];

    // ---- Exact recheck (global cb rows; R1 bit-exact d2; first-index ties) ----
    int bi = 0;
    {
        const int cnt = cand_cnt[tid];
        float bestE = 3.4e38f;
        if (cnt <= CANDCAP) {
            for (int i = 0; i < cnt; i++) {
                const int k = cand[tid * CANDCAP + i];
                const float4* qr = reinterpret_cast<const float4*>(cb + k * DIM);
                float dotx = 0.0f;
                #pragma unroll
                for (int jj = 0; jj < 8; jj++) {
                    float4 q4 = __ldg(qr + jj);
                    dotx = __fmaf_rn(xr[4*jj+0], q4.x, dotx);
                    dotx = __fmaf_rn(xr[4*jj+1], q4.y, dotx);
                    dotx = __fmaf_rn(xr[4*jj+2], q4.z, dotx);
                    dotx = __fmaf_rn(xr[4*jj+3], q4.w, dotx);
                }
                float d2 = __fadd_rn(__fadd_rn(x2, __fmul_rn(-2.0f, dotx)), c2_s[k]);
                if (d2 < bestE || (d2 == bestE && k < bi)) { bestE = d2; bi = k; }
            }
        } else {
            // overflow: deterministic full exact scan, ascending k, strict <
            for (int k = 0; k < KCODES; k++) {
                const float4* qr = reinterpret_cast<const float4*>(cb + k * DIM);
                float dotx = 0.0f;
                #pragma unroll
                for (int jj = 0; jj < 8; jj++) {
                    float4 q4 = __ldg(qr + jj);
                    dotx = __fmaf_rn(xr[4*jj+0], q4.x, dotx);
                    dotx = __fmaf_rn(xr[4*jj+1], q4.y, dotx);
                    dotx = __fmaf_rn(xr[4*jj+2], q4.z, dotx);
                    dotx = __fmaf_rn(xr[4*jj+3], q4.w, dotx);
                }
                float d2 = __fadd_rn(__fadd_rn(x2, __fmul_rn(-2.0f, dotx)), c2_s[k]);
                if (d2 < bestE) { bestE = d2; bi = k; }
            }
        }
    }

    // ---- Epilogue: histogram + rotation-trick output (exact q from global) ----
    atomicAdd(&hist[bi], 1.0f);
    {
        float qv[DIM];
        const float4* qrow = reinterpret_cast<const float4*>(cb + bi * DIM);
        #pragma unroll
        for (int j = 0; j < 8; j++) {
            float4 v = __ldg(qrow + j);
            qv[4*j+0] = v.x; qv[4*j+1] = v.y; qv[4*j+2] = v.z; qv[4*j+3] = v.w;
        }
        float q2 = 0.f, dotq = 0.f;
        #pragma unroll
        for (int d = 0; d < DIM; d++) {
            q2   = __fmaf_rn(qv[d], qv[d], q2);
            dotq = __fmaf_rn(xr[d], qv[d], dotq);
        }
        const float eps = 1e-6f;
        float inx = 1.0f / fmaxf(sqrtf(x2), eps);
        float inq = 1.0f / fmaxf(sqrtf(q2), eps);
        float u2  = x2 * inx * inx;
        float qh2 = q2 * inq * inq;
        float uq  = dotq * inx * inq;
        float w2  = u2 + qh2 + 2.0f * uq;
        float iw  = 1.0f / fmaxf(sqrtf(w2), eps);
        float ew  = (x2 * inx + dotq * inq) * iw;
        float eu  = x2 * inx;
        float a   = -2.0f * ew * iw;
        float s1  = 1.0f + a * inx;
        float s2  = (a + 2.0f * eu) * inq;

        float4* rp = reinterpret_cast<float4*>(out_rot + (tok0 + tid) * DIM);
        #pragma unroll
        for (int j = 0; j < 8; j++) {
            float4 v;
            v.x = xr[4*j+0] * s1 + qv[4*j+0] * s2;
            v.y = xr[4*j+1] * s1 + qv[4*j+1] * s2;
            v.z = xr[4*j+2] * s1 + qv[4*j+2] * s2;
            v.w = xr[4*j+3] * s1 + qv[4*j+3] * s2;
            rp[j] = v;
        }
        out_idx[tok0 + tid] = (float)bi;
    }

    // ---- Flush histogram ----
    __syncthreads();
    #pragma unroll
    for (int rr = 0; rr < 2; rr++)
        atomicAdd(&out_counts[tid + rr * TPB], hist[tid + rr * TPB]);
}

extern "C" void kernel_launch(void* const* d_in, const int* in_sizes, int n_in,
                              void* d_out, int out_size) {
    const float* x  = (const float*)d_in[0];
    const float* cb = (const float*)d_in[1];
    float* out = (float*)d_out;

    const int N = in_sizes[0] / DIM;            // 524288
    float* rot    = out;
    float* idx    = out + (size_t)N * DIM;
    float* counts = idx + N;

    const int dyn = (TPB * XST + KCODES * CST) * 4;  // 51712 B
    cudaFuncSetAttribute(vq_tc, cudaFuncAttributeMaxDynamicSharedMemorySize, dyn);
    vq_zero_counts<<<1, KCODES>>>(counts);
    vq_tc<<<NTILES, TPB, dyn>>>(x, cb, rot, idx, counts);
}